// round 2
// baseline (speedup 1.0000x reference)
#include <cuda_runtime.h>
#include <math.h>
#include <stdint.h>

#define BATCH 16384
#define DIN   512
#define HID   64
#define CDIM  256
#define KPROT 2048

// ---------------- scratch (no allocations allowed) ----------------
static __device__ float g_h1[BATCH * HID];
static __device__ float g_h2[BATCH * HID];
static __device__ float g_h3[BATCH * CDIM];
static __device__ float g_mu[BATCH * CDIM];
static __device__ float g_musq[BATCH];
static __device__ float g_psq[KPROT];
static __device__ float g_lse[BATCH];
static __device__ float g_negd[(size_t)BATCH * KPROT];   // 128 MB
static __device__ float g_cs_exp[KPROT];
static __device__ float g_cs_nd[KPROT];
static __device__ float g_sum_lse_d;

// ---------------- zero accumulators ----------------
__global__ void k_zero() {
    int t = blockIdx.x * 256 + threadIdx.x;
    if (t < KPROT) { g_cs_exp[t] = 0.f; g_cs_nd[t] = 0.f; }
    if (t == 0) g_sum_lse_d = 0.f;
}

// ---------------- generic register-tiled SGEMM + bias (+relu) ----------------
// C[M,N] = A[M,KD] @ B[KD,N] + bias  (B row-major [KD,N])
template<int M, int N, int KD, int BM, int BN, int BK, int TM, int TN, bool RELU>
__global__ void __launch_bounds__((BM / TM) * (BN / TN))
k_sgemm(const float* __restrict__ A, const float* __restrict__ B,
        const float* __restrict__ bias, float* __restrict__ C)
{
    constexpr int NT = (BM / TM) * (BN / TN);
    __shared__ float As[BK][BM];
    __shared__ float Bs[BK][BN];
    const int tid = threadIdx.x;
    const int tx  = tid % (BN / TN);
    const int ty  = tid / (BN / TN);
    const int m0  = blockIdx.y * BM;
    const int n0  = blockIdx.x * BN;

    float acc[TM][TN];
#pragma unroll
    for (int i = 0; i < TM; i++)
#pragma unroll
        for (int j = 0; j < TN; j++) acc[i][j] = 0.f;

    for (int k0 = 0; k0 < KD; k0 += BK) {
#pragma unroll
        for (int i = 0; i < (BM * BK) / NT; i++) {
            int e = tid + i * NT;
            int m = e / BK, k = e % BK;
            As[k][m] = A[(size_t)(m0 + m) * KD + k0 + k];
        }
#pragma unroll
        for (int i = 0; i < (BK * BN) / NT; i++) {
            int e = tid + i * NT;
            int k = e / BN, n = e % BN;
            Bs[k][n] = B[(size_t)(k0 + k) * N + n0 + n];
        }
        __syncthreads();
#pragma unroll
        for (int k = 0; k < BK; k++) {
            float a[TM], b[TN];
#pragma unroll
            for (int i = 0; i < TM; i++) a[i] = As[k][ty * TM + i];
#pragma unroll
            for (int j = 0; j < TN; j++) b[j] = Bs[k][tx * TN + j];
#pragma unroll
            for (int i = 0; i < TM; i++)
#pragma unroll
                for (int j = 0; j < TN; j++) acc[i][j] = fmaf(a[i], b[j], acc[i][j]);
        }
        __syncthreads();
    }
#pragma unroll
    for (int i = 0; i < TM; i++) {
        int row = m0 + ty * TM + i;
#pragma unroll
        for (int j = 0; j < TN; j++) {
            int col = n0 + tx * TN + j;
            float v = acc[i][j] + bias[col];
            if (RELU) v = fmaxf(v, 0.f);
            C[(size_t)row * N + col] = v;
        }
    }
}

// ---------------- neg_d GEMM: ND[m,n] = 2*sum_k MU[m,k]*P[n,k] - musq[m] - psq[n] ----
template<int BM, int BN, int BK, int TM, int TN>
__global__ void __launch_bounds__((BM / TM) * (BN / TN))
k_negd(const float* __restrict__ MU, const float* __restrict__ P,
       const float* __restrict__ musq, const float* __restrict__ psq)
{
    constexpr int NT = (BM / TM) * (BN / TN);
    __shared__ float As[BK][BM];
    __shared__ float Bs[BK][BN];
    const int tid = threadIdx.x;
    const int tx  = tid % (BN / TN);
    const int ty  = tid / (BN / TN);
    const int m0  = blockIdx.y * BM;
    const int n0  = blockIdx.x * BN;

    float acc[TM][TN];
#pragma unroll
    for (int i = 0; i < TM; i++)
#pragma unroll
        for (int j = 0; j < TN; j++) acc[i][j] = 0.f;

    for (int k0 = 0; k0 < CDIM; k0 += BK) {
#pragma unroll
        for (int i = 0; i < (BM * BK) / NT; i++) {
            int e = tid + i * NT;
            int m = e / BK, k = e % BK;
            As[k][m] = MU[(size_t)(m0 + m) * CDIM + k0 + k];
        }
#pragma unroll
        for (int i = 0; i < (BK * BN) / NT; i++) {
            int e = tid + i * NT;
            int n = e / BK, k = e % BK;
            Bs[k][n] = P[(size_t)(n0 + n) * CDIM + k0 + k];
        }
        __syncthreads();
#pragma unroll
        for (int k = 0; k < BK; k++) {
            float a[TM], b[TN];
#pragma unroll
            for (int i = 0; i < TM; i++) a[i] = As[k][ty * TM + i];
#pragma unroll
            for (int j = 0; j < TN; j++) b[j] = Bs[k][tx * TN + j];
#pragma unroll
            for (int i = 0; i < TM; i++)
#pragma unroll
                for (int j = 0; j < TN; j++) acc[i][j] = fmaf(a[i], b[j], acc[i][j]);
        }
        __syncthreads();
    }
#pragma unroll
    for (int i = 0; i < TM; i++) {
        int row = m0 + ty * TM + i;
        float ms = musq[row];
#pragma unroll
        for (int j = 0; j < TN; j++) {
            int col = n0 + tx * TN + j;
            g_negd[(size_t)row * KPROT + col] = 2.f * acc[i][j] - ms - psq[col];
        }
    }
}

// ---------------- per-row sum of squares (one warp per row) ----------------
__global__ void k_rowsq(const float* __restrict__ X, float* __restrict__ out, int ncols)
{
    int row  = blockIdx.x * 8 + (threadIdx.x >> 5);
    int lane = threadIdx.x & 31;
    const float* p = X + (size_t)row * ncols;
    float s = 0.f;
    for (int c = lane; c < ncols; c += 32) { float v = p[c]; s = fmaf(v, v, s); }
#pragma unroll
    for (int o = 16; o > 0; o >>= 1) s += __shfl_xor_sync(0xffffffffu, s, o);
    if (lane == 0) out[row] = s;
}

// ---------------- per-row: lse, argmax(neg_d+gumbel), quantized gather ----------------
__global__ void __launch_bounds__(256) k_rowfin(const float* __restrict__ gumbel,
                                               const float* __restrict__ protos,
                                               float* __restrict__ outq)
{
    __shared__ float sL[8];
    int warp = threadIdx.x >> 5, lane = threadIdx.x & 31;
    int row  = blockIdx.x * 8 + warp;
    const float* nd = g_negd + (size_t)row * KPROT;
    const float* gb = gumbel + (size_t)row * KPROT;

    float vv[KPROT / 32];
    float m1 = -3.402823466e38f, m2 = -3.402823466e38f;
    int arg = 0;
#pragma unroll
    for (int i = 0; i < KPROT / 32; i++) {
        int c = lane + i * 32;
        float v = nd[c];
        vv[i] = v;
        m1 = fmaxf(m1, v);
        float t = v + gb[c];
        if (t > m2) { m2 = t; arg = c; }
    }
    // warp argmax reduce (first index wins ties, matching jnp.argmax)
#pragma unroll
    for (int o = 16; o > 0; o >>= 1) {
        float om = __shfl_xor_sync(0xffffffffu, m2, o);
        int   oa = __shfl_xor_sync(0xffffffffu, arg, o);
        if (om > m2 || (om == m2 && oa < arg)) { m2 = om; arg = oa; }
    }
#pragma unroll
    for (int o = 16; o > 0; o >>= 1) m1 = fmaxf(m1, __shfl_xor_sync(0xffffffffu, m1, o));
    float s = 0.f;
#pragma unroll
    for (int i = 0; i < KPROT / 32; i++) s += __expf(vv[i] - m1);
#pragma unroll
    for (int o = 16; o > 0; o >>= 1) s += __shfl_xor_sync(0xffffffffu, s, o);
    float lse = m1 + logf(s);
    if (lane == 0) { g_lse[row] = lse; sL[warp] = lse; }

    // quantized row = protos[arg]  (exact: hard + soft - stop_grad(soft) == hard)
    const float* pr = protos + (size_t)arg * CDIM;
    float* o = outq + (size_t)row * CDIM;
#pragma unroll
    for (int i = 0; i < CDIM / 32; i++) o[lane + i * 32] = pr[lane + i * 32];

    __syncthreads();
    if (threadIdx.x == 0) {
        float t = 0.f;
#pragma unroll
        for (int r = 0; r < 8; r++) t += sL[r];
        atomicAdd(&g_sum_lse_d, t);
    }
}

// ---------------- column sums: sum_b exp(nd-lse), sum_b nd ----------------
__global__ void __launch_bounds__(256) k_colsum()
{
    __shared__ float sL[16];
    int row0 = blockIdx.x * 16;
    if (threadIdx.x < 16) sL[threadIdx.x] = g_lse[row0 + threadIdx.x];
    __syncthreads();
#pragma unroll
    for (int cc = 0; cc < KPROT / 256; cc++) {
        int c = threadIdx.x + cc * 256;
        float se = 0.f, sn = 0.f;
#pragma unroll
        for (int r = 0; r < 16; r++) {
            float v = g_negd[(size_t)(row0 + r) * KPROT + c];
            se += __expf(v - sL[r]);
            sn += v;
        }
        atomicAdd(&g_cs_exp[c], se);
        atomicAdd(&g_cs_nd[c], sn);
    }
}

// ---------------- final loss scalar ----------------
__global__ void k_loss(float* __restrict__ out, int loss_idx)
{
    __shared__ float r1[256], r2[256];
    int tid = threadIdx.x;
    const float inv = 1.f / (float)BATCH;
    float mean_lse = g_sum_lse_d * inv;
    float c1 = 0.f, c2 = 0.f;
    for (int k = tid; k < KPROT; k += 256) {
        float prior = g_cs_exp[k] * inv + 1e-6f;
        float Mk    = g_cs_nd[k] * inv - mean_lse;   // mean_b logprobs[:,k]
        float lp    = logf(prior);
        c1 += prior * lp;
        c2 += prior * Mk;
    }
    r1[tid] = c1; r2[tid] = c2;
    __syncthreads();
    for (int o = 128; o > 0; o >>= 1) {
        if (tid < o) { r1[tid] += r1[tid + o]; r2[tid] += r2[tid + o]; }
        __syncthreads();
    }
    if (tid == 0) {
        float capacity = r1[0] - r2[0];
        float ent      = -r1[0];
        out[loss_idx]  = 0.01f * capacity + (-0.001f) * ent;
    }
}

// ---------------- launch ----------------
extern "C" void kernel_launch(void* const* d_in, const int* in_sizes, int n_in,
                              void* d_out, int out_size)
{
    (void)in_sizes; (void)n_in;
    const float* x      = (const float*)d_in[0];
    const float* gumbel = (const float*)d_in[1];
    const float* W_emb  = (const float*)d_in[2];
    const float* b_emb  = (const float*)d_in[3];
    const float* W0     = (const float*)d_in[4];
    const float* b0     = (const float*)d_in[5];
    const float* W1     = (const float*)d_in[6];
    const float* b1     = (const float*)d_in[7];
    const float* W_mu   = (const float*)d_in[8];
    const float* b_mu   = (const float*)d_in[9];
    // d_in[10], d_in[11] = W_var, b_var: unused downstream (dead code in ref)
    const float* protos = (const float*)d_in[12];
    float* out = (float*)d_out;

    float *h1, *h2, *h3, *mu, *musq, *psq;
    cudaGetSymbolAddress((void**)&h1,   g_h1);
    cudaGetSymbolAddress((void**)&h2,   g_h2);
    cudaGetSymbolAddress((void**)&h3,   g_h3);
    cudaGetSymbolAddress((void**)&mu,   g_mu);
    cudaGetSymbolAddress((void**)&musq, g_musq);
    cudaGetSymbolAddress((void**)&psq,  g_psq);

    k_zero<<<(KPROT + 255) / 256, 256>>>();

    // MLP: h1 = x@W_emb+b ; h2 = relu(h1@W0+b) ; h3 = relu(h2@W1+b) ; mu = h3@W_mu+b
    k_sgemm<BATCH, HID,  DIN,  128, 64, 8, 8, 4, false><<<dim3(1, BATCH / 128), 256>>>(x,  W_emb, b_emb, h1);
    k_sgemm<BATCH, HID,  HID,  128, 64, 8, 8, 4, true ><<<dim3(1, BATCH / 128), 256>>>(h1, W0,    b0,    h2);
    k_sgemm<BATCH, CDIM, HID,  128, 64, 8, 8, 4, true ><<<dim3(4, BATCH / 128), 256>>>(h2, W1,    b1,    h3);
    k_sgemm<BATCH, CDIM, CDIM, 128, 64, 8, 8, 4, false><<<dim3(4, BATCH / 128), 256>>>(h3, W_mu,  b_mu,  mu);

    k_rowsq<<<BATCH / 8, 256>>>(mu,     musq, CDIM);
    k_rowsq<<<KPROT / 8, 256>>>(protos, psq,  CDIM);

    // neg_d = 2*mu@protos^T - ||mu||^2 - ||p||^2
    k_negd<128, 128, 8, 8, 8><<<dim3(KPROT / 128, BATCH / 128), 256>>>(mu, protos, musq, psq);

    // per-row lse / argmax(neg_d+gumbel) / gather quantized rows
    k_rowfin<<<BATCH / 8, 256>>>(gumbel, protos, out);

    // per-proto column sums for prior / mean logprobs
    k_colsum<<<BATCH / 16, 256>>>();

    // scalar loss at the tail of the output buffer
    k_loss<<<1, 256>>>(out, out_size - 1);
}

// round 4
// speedup vs baseline: 3.2846x; 3.2846x over previous
#include <cuda_runtime.h>
#include <cuda_bf16.h>
#include <math.h>
#include <stdint.h>

#define BATCH 16384
#define DIN   512
#define HID   64
#define CDIM  256
#define KPROT 2048

// ---------------- scratch (no allocations allowed) ----------------
static __device__ float g_h1[BATCH * HID];
static __device__ __nv_bfloat16 g_h2bf[BATCH * HID];
static __device__ __nv_bfloat16 g_h3bf[BATCH * CDIM];
static __device__ __nv_bfloat16 g_mubf[BATCH * CDIM];
static __device__ __nv_bfloat16 g_protosbf[KPROT * CDIM];
static __device__ __nv_bfloat16 g_WmuT[CDIM * CDIM];
static __device__ __nv_bfloat16 g_W1T[CDIM * HID];
static __device__ float g_musq[BATCH];
static __device__ float g_psq[KPROT];
static __device__ float g_lse[BATCH];
static __device__ float g_negd[(size_t)BATCH * KPROT];   // 128 MB
static __device__ float g_cs_exp[KPROT];
static __device__ float g_cs_nd[KPROT];
static __device__ float g_sum_lse_d;

// ---------------- helpers ----------------
__device__ __forceinline__ uint32_t smem_to_u32(const void* p) {
    uint32_t a;
    asm("{ .reg .u64 t; cvta.to.shared.u64 t, %1; cvt.u32.u64 %0, t; }" : "=r"(a) : "l"(p));
    return a;
}
#define LDMATRIX_X4(R, addr) \
    asm volatile("ldmatrix.sync.aligned.m8n8.x4.shared.b16 {%0,%1,%2,%3}, [%4];" \
        : "=r"((R)[0]), "=r"((R)[1]), "=r"((R)[2]), "=r"((R)[3]) : "r"(addr))
#define MMA_BF16(D, A, B0, B1) \
    asm volatile("mma.sync.aligned.m16n8k16.row.col.f32.bf16.bf16.f32 " \
        "{%0,%1,%2,%3}, {%4,%5,%6,%7}, {%8,%9}, {%0,%1,%2,%3};" \
        : "+f"((D)[0]), "+f"((D)[1]), "+f"((D)[2]), "+f"((D)[3]) \
        : "r"((A)[0]), "r"((A)[1]), "r"((A)[2]), "r"((A)[3]), "r"(B0), "r"(B1))

// ---------------- zero accumulators ----------------
__global__ void k_zero() {
    int t = blockIdx.x * 256 + threadIdx.x;
    if (t < BATCH) g_musq[t] = 0.f;
    if (t < KPROT) { g_cs_exp[t] = 0.f; g_cs_nd[t] = 0.f; }
    if (t == 0) g_sum_lse_d = 0.f;
}

// ---------------- bf16 conversions ----------------
__global__ void k_cvt_protos(const float* __restrict__ p) {
    int i = blockIdx.x * 256 + threadIdx.x;
    g_protosbf[i] = __float2bfloat16(p[i]);
}
__global__ void k_cvt_wmuT(const float* __restrict__ W) {   // W_mu [256][256] -> [n][k]
    int n = blockIdx.x, k = threadIdx.x;
    g_WmuT[n * CDIM + k] = __float2bfloat16(W[(size_t)k * CDIM + n]);
}
__global__ void k_cvt_w1T(const float* __restrict__ W) {    // W1 [64][256] -> [n][k]
    int n = blockIdx.x, k = threadIdx.x;
    g_W1T[n * HID + k] = __float2bfloat16(W[(size_t)k * CDIM + n]);
}

// ---------------- fp32 register-tiled SGEMM + bias (+relu) (h1, h2) --------
template<int M, int N, int KD, int BM, int BN, int BK, int TM, int TN, bool RELU, bool OUT_BF16>
__global__ void __launch_bounds__((BM / TM) * (BN / TN))
k_sgemm(const float* __restrict__ A, const float* __restrict__ B,
        const float* __restrict__ bias, void* __restrict__ Cv)
{
    constexpr int NT = (BM / TM) * (BN / TN);
    __shared__ float As[BK][BM];
    __shared__ float Bs[BK][BN];
    const int tid = threadIdx.x;
    const int tx  = tid % (BN / TN);
    const int ty  = tid / (BN / TN);
    const int m0  = blockIdx.y * BM;
    const int n0  = blockIdx.x * BN;

    float acc[TM][TN];
#pragma unroll
    for (int i = 0; i < TM; i++)
#pragma unroll
        for (int j = 0; j < TN; j++) acc[i][j] = 0.f;

    for (int k0 = 0; k0 < KD; k0 += BK) {
#pragma unroll
        for (int i = 0; i < (BM * BK) / NT; i++) {
            int e = tid + i * NT;
            int m = e / BK, k = e % BK;
            As[k][m] = A[(size_t)(m0 + m) * KD + k0 + k];
        }
#pragma unroll
        for (int i = 0; i < (BK * BN) / NT; i++) {
            int e = tid + i * NT;
            int k = e / BN, n = e % BN;
            Bs[k][n] = B[(size_t)(k0 + k) * N + n0 + n];
        }
        __syncthreads();
#pragma unroll
        for (int k = 0; k < BK; k++) {
            float a[TM], b[TN];
#pragma unroll
            for (int i = 0; i < TM; i++) a[i] = As[k][ty * TM + i];
#pragma unroll
            for (int j = 0; j < TN; j++) b[j] = Bs[k][tx * TN + j];
#pragma unroll
            for (int i = 0; i < TM; i++)
#pragma unroll
                for (int j = 0; j < TN; j++) acc[i][j] = fmaf(a[i], b[j], acc[i][j]);
        }
        __syncthreads();
    }
#pragma unroll
    for (int i = 0; i < TM; i++) {
        int row = m0 + ty * TM + i;
#pragma unroll
        for (int j = 0; j < TN; j++) {
            int col = n0 + tx * TN + j;
            float v = acc[i][j] + bias[col];
            if (RELU) v = fmaxf(v, 0.f);
            if (OUT_BF16)
                ((__nv_bfloat16*)Cv)[(size_t)row * N + col] = __float2bfloat16(v);
            else
                ((float*)Cv)[(size_t)row * N + col] = v;
        }
    }
}

// ---------------- bf16 HMMA GEMM (mma.sync m16n8k16), D = A @ B^T ----------
// A [*, KDIM] row-major bf16, B [*, KDIM] row-major bf16 (i.e. B^T col-major).
// Tile 128x128, BK=32, 8 warps (4 along M x 2 along N), 2 CTAs/SM.
// EPI: 0 = NEGD  (outf[r,c] = 2*acc - rowterm[r] - colterm[c])
//      1 = MU    (v = acc + colterm[c]; outbf = bf16(v); atomicAdd(musq_acc[r], v^2))
//      2 = RELU  (v = max(acc + colterm[c], 0); outbf = bf16(v))
template<int KDIM, int EPI>
__global__ void __launch_bounds__(256, 2)
k_hmma(const __nv_bfloat16* __restrict__ A, const __nv_bfloat16* __restrict__ B,
       const float* __restrict__ colterm, const float* __restrict__ rowterm,
       float* __restrict__ musq_acc,
       float* __restrict__ outf, __nv_bfloat16* __restrict__ outbf, int ldOut)
{
    constexpr int NITER = KDIM / 32;
    __shared__ __align__(16) uint8_t As[128 * 80];   // 32 bf16 per row, stride 80B
    __shared__ __align__(16) uint8_t Bs[128 * 80];

    const int tid  = threadIdx.x;
    const int lane = tid & 31;
    const int wid  = tid >> 5;
    const int wm   = wid & 3;       // warp row block (32 rows)
    const int wn   = wid >> 2;      // warp col block (64 cols)
    const int m0   = blockIdx.y * 128;
    const int n0   = blockIdx.x * 128;
    const uint32_t asb = smem_to_u32(As);
    const uint32_t bsb = smem_to_u32(Bs);

    // gmem<->smem tile staging: thread owns rows lrow, lrow+64 at 16B chunk lch
    const int lrow = tid >> 2;
    const int lch  = tid & 3;
    const uint4* pa0 = (const uint4*)(A + (size_t)(m0 + lrow)      * KDIM);
    const uint4* pa1 = (const uint4*)(A + (size_t)(m0 + lrow + 64) * KDIM);
    const uint4* pb0 = (const uint4*)(B + (size_t)(n0 + lrow)      * KDIM);
    const uint4* pb1 = (const uint4*)(B + (size_t)(n0 + lrow + 64) * KDIM);
    uint4* sa0 = (uint4*)(As + lrow * 80 + lch * 16);
    uint4* sa1 = (uint4*)(As + (lrow + 64) * 80 + lch * 16);
    uint4* sb0 = (uint4*)(Bs + lrow * 80 + lch * 16);
    uint4* sb1 = (uint4*)(Bs + (lrow + 64) * 80 + lch * 16);

    *sa0 = pa0[lch]; *sa1 = pa1[lch];
    *sb0 = pb0[lch]; *sb1 = pb1[lch];
    __syncthreads();

    float acc[2][8][4];
#pragma unroll
    for (int i = 0; i < 2; i++)
#pragma unroll
        for (int j = 0; j < 8; j++)
#pragma unroll
            for (int q = 0; q < 4; q++) acc[i][j][q] = 0.f;

    // ldmatrix lane addressing within the 32-col smem tile
    const uint32_t aoff = (uint32_t)((wm * 32 + (lane & 15)) * 80 + (lane >> 4) * 16);
    const uint32_t boff = (uint32_t)((wn * 64 + ((lane >> 4) & 1) * 8 + (lane & 7)) * 80
                                     + ((lane >> 3) & 1) * 16);

    for (int it = 0; it < NITER; it++) {
        uint4 fa0, fa1, fb0, fb1;
        if (it + 1 < NITER) {
            int ku = (it + 1) * 4 + lch;
            fa0 = pa0[ku]; fa1 = pa1[ku];
            fb0 = pb0[ku]; fb1 = pb1[ku];
        }
#pragma unroll
        for (int ks = 0; ks < 2; ks++) {
            uint32_t af[2][4], bfr[4][4];
            LDMATRIX_X4(af[0], asb + aoff + ks * 32);
            LDMATRIX_X4(af[1], asb + aoff + 16 * 80 + ks * 32);
#pragma unroll
            for (int p = 0; p < 4; p++)
                LDMATRIX_X4(bfr[p], bsb + boff + p * (16 * 80) + ks * 32);
#pragma unroll
            for (int im = 0; im < 2; im++)
#pragma unroll
                for (int jn = 0; jn < 8; jn++)
                    MMA_BF16(acc[im][jn], af[im],
                             bfr[jn >> 1][(jn & 1) * 2], bfr[jn >> 1][(jn & 1) * 2 + 1]);
        }
        __syncthreads();
        if (it + 1 < NITER) {
            *sa0 = fa0; *sa1 = fa1; *sb0 = fb0; *sb1 = fb1;
            __syncthreads();
        }
    }

    // ---- epilogue ----
    const int r_base = m0 + wm * 32 + (lane >> 2);
    const int c_base = n0 + wn * 64 + (lane & 3) * 2;
#pragma unroll
    for (int im = 0; im < 2; im++) {
        const int r0 = r_base + im * 16;
        const int r1 = r0 + 8;
        float ms0 = 0.f, ms1 = 0.f, ss0 = 0.f, ss1 = 0.f;
        if (EPI == 0) { ms0 = rowterm[r0]; ms1 = rowterm[r1]; }
#pragma unroll
        for (int jn = 0; jn < 8; jn++) {
            const int c = c_base + jn * 8;
            const float ct0 = colterm[c], ct1 = colterm[c + 1];
            if (EPI == 0) {
                float2 v0, v1;
                v0.x = 2.f * acc[im][jn][0] - ms0 - ct0;
                v0.y = 2.f * acc[im][jn][1] - ms0 - ct1;
                v1.x = 2.f * acc[im][jn][2] - ms1 - ct0;
                v1.y = 2.f * acc[im][jn][3] - ms1 - ct1;
                *(float2*)(outf + (size_t)r0 * ldOut + c) = v0;
                *(float2*)(outf + (size_t)r1 * ldOut + c) = v1;
            } else {
                float v00 = acc[im][jn][0] + ct0;
                float v01 = acc[im][jn][1] + ct1;
                float v10 = acc[im][jn][2] + ct0;
                float v11 = acc[im][jn][3] + ct1;
                if (EPI == 2) {
                    v00 = fmaxf(v00, 0.f); v01 = fmaxf(v01, 0.f);
                    v10 = fmaxf(v10, 0.f); v11 = fmaxf(v11, 0.f);
                } else {
                    ss0 = fmaf(v00, v00, ss0); ss0 = fmaf(v01, v01, ss0);
                    ss1 = fmaf(v10, v10, ss1); ss1 = fmaf(v11, v11, ss1);
                }
                *(__nv_bfloat162*)(outbf + (size_t)r0 * ldOut + c) = __floats2bfloat162_rn(v00, v01);
                *(__nv_bfloat162*)(outbf + (size_t)r1 * ldOut + c) = __floats2bfloat162_rn(v10, v11);
            }
        }
        if (EPI == 1) {
            atomicAdd(&musq_acc[r0], ss0);
            atomicAdd(&musq_acc[r1], ss1);
        }
    }
}

// ---------------- per-row sum of squares (one warp per row) ----------------
__global__ void k_rowsq(const float* __restrict__ X, float* __restrict__ out, int ncols)
{
    int row  = blockIdx.x * 8 + (threadIdx.x >> 5);
    int lane = threadIdx.x & 31;
    const float* p = X + (size_t)row * ncols;
    float s = 0.f;
    for (int c = lane; c < ncols; c += 32) { float v = p[c]; s = fmaf(v, v, s); }
#pragma unroll
    for (int o = 16; o > 0; o >>= 1) s += __shfl_xor_sync(0xffffffffu, s, o);
    if (lane == 0) out[row] = s;
}

// ---------------- per-row: lse, argmax(neg_d+gumbel), quantized gather ------
__global__ void __launch_bounds__(256) k_rowfin(const float* __restrict__ gumbel,
                                               const float* __restrict__ protos,
                                               float* __restrict__ outq)
{
    __shared__ float sL[8];
    int warp = threadIdx.x >> 5, lane = threadIdx.x & 31;
    int row  = blockIdx.x * 8 + warp;
    const float* nd = g_negd + (size_t)row * KPROT;
    const float* gb = gumbel + (size_t)row * KPROT;

    float vv[KPROT / 32];
    float m1 = -3.402823466e38f, m2 = -3.402823466e38f;
    int arg = 0;
#pragma unroll
    for (int i = 0; i < KPROT / 32; i++) {
        int c = lane + i * 32;
        float v = nd[c];
        vv[i] = v;
        m1 = fmaxf(m1, v);
        float t = v + gb[c];
        if (t > m2) { m2 = t; arg = c; }
    }
#pragma unroll
    for (int o = 16; o > 0; o >>= 1) {
        float om = __shfl_xor_sync(0xffffffffu, m2, o);
        int   oa = __shfl_xor_sync(0xffffffffu, arg, o);
        if (om > m2 || (om == m2 && oa < arg)) { m2 = om; arg = oa; }
    }
#pragma unroll
    for (int o = 16; o > 0; o >>= 1) m1 = fmaxf(m1, __shfl_xor_sync(0xffffffffu, m1, o));
    float s = 0.f;
#pragma unroll
    for (int i = 0; i < KPROT / 32; i++) s += __expf(vv[i] - m1);
#pragma unroll
    for (int o = 16; o > 0; o >>= 1) s += __shfl_xor_sync(0xffffffffu, s, o);
    float lse = m1 + logf(s);
    if (lane == 0) { g_lse[row] = lse; sL[warp] = lse; }

    const float* pr = protos + (size_t)arg * CDIM;
    float* o = outq + (size_t)row * CDIM;
#pragma unroll
    for (int i = 0; i < CDIM / 32; i++) o[lane + i * 32] = pr[lane + i * 32];

    __syncthreads();
    if (threadIdx.x == 0) {
        float t = 0.f;
#pragma unroll
        for (int r = 0; r < 8; r++) t += sL[r];
        atomicAdd(&g_sum_lse_d, t);
    }
}

// ---------------- column sums: sum_b exp(nd-lse), sum_b nd ----------------
__global__ void __launch_bounds__(256) k_colsum()
{
    __shared__ float sL[16];
    int row0 = blockIdx.x * 16;
    if (threadIdx.x < 16) sL[threadIdx.x] = g_lse[row0 + threadIdx.x];
    __syncthreads();
#pragma unroll
    for (int cc = 0; cc < KPROT / 256; cc++) {
        int c = threadIdx.x + cc * 256;
        float se = 0.f, sn = 0.f;
#pragma unroll
        for (int r = 0; r < 16; r++) {
            float v = g_negd[(size_t)(row0 + r) * KPROT + c];
            se += __expf(v - sL[r]);
            sn += v;
        }
        atomicAdd(&g_cs_exp[c], se);
        atomicAdd(&g_cs_nd[c], sn);
    }
}

// ---------------- final loss scalar ----------------
__global__ void k_loss(float* __restrict__ out, int loss_idx)
{
    __shared__ float r1[256], r2[256];
    int tid = threadIdx.x;
    const float inv = 1.f / (float)BATCH;
    float mean_lse = g_sum_lse_d * inv;
    float c1 = 0.f, c2 = 0.f;
    for (int k = tid; k < KPROT; k += 256) {
        float prior = g_cs_exp[k] * inv + 1e-6f;
        float Mk    = g_cs_nd[k] * inv - mean_lse;
        float lp    = logf(prior);
        c1 += prior * lp;
        c2 += prior * Mk;
    }
    r1[tid] = c1; r2[tid] = c2;
    __syncthreads();
    for (int o = 128; o > 0; o >>= 1) {
        if (tid < o) { r1[tid] += r1[tid + o]; r2[tid] += r2[tid + o]; }
        __syncthreads();
    }
    if (tid == 0) {
        float capacity = r1[0] - r2[0];
        float ent      = -r1[0];
        out[loss_idx]  = 0.01f * capacity + (-0.001f) * ent;
    }
}

// ---------------- launch ----------------
extern "C" void kernel_launch(void* const* d_in, const int* in_sizes, int n_in,
                              void* d_out, int out_size)
{
    (void)in_sizes; (void)n_in;
    const float* x      = (const float*)d_in[0];
    const float* gumbel = (const float*)d_in[1];
    const float* W_emb  = (const float*)d_in[2];
    const float* b_emb  = (const float*)d_in[3];
    const float* W0     = (const float*)d_in[4];
    const float* b0     = (const float*)d_in[5];
    const float* W1     = (const float*)d_in[6];
    const float* b1     = (const float*)d_in[7];
    const float* W_mu   = (const float*)d_in[8];
    const float* b_mu   = (const float*)d_in[9];
    // d_in[10], d_in[11] = W_var, b_var: dead code in the reference
    const float* protos = (const float*)d_in[12];
    float* out = (float*)d_out;

    float *h1, *musq, *psq, *negd;
    __nv_bfloat16 *h2bf, *h3bf, *mubf, *protosbf, *wmuT, *w1T;
    cudaGetSymbolAddress((void**)&h1,       g_h1);
    cudaGetSymbolAddress((void**)&h2bf,     g_h2bf);
    cudaGetSymbolAddress((void**)&h3bf,     g_h3bf);
    cudaGetSymbolAddress((void**)&mubf,     g_mubf);
    cudaGetSymbolAddress((void**)&protosbf, g_protosbf);
    cudaGetSymbolAddress((void**)&wmuT,     g_WmuT);
    cudaGetSymbolAddress((void**)&w1T,      g_W1T);
    cudaGetSymbolAddress((void**)&musq,     g_musq);
    cudaGetSymbolAddress((void**)&psq,      g_psq);
    cudaGetSymbolAddress((void**)&negd,     g_negd);

    k_zero<<<BATCH / 256, 256>>>();
    k_cvt_protos<<<(KPROT * CDIM) / 256, 256>>>(protos);
    k_cvt_wmuT<<<CDIM, CDIM>>>(W_mu);
    k_cvt_w1T<<<CDIM, HID>>>(W1);
    k_rowsq<<<KPROT / 8, 256>>>(protos, psq, CDIM);

    // MLP head: h1 = x@W_emb+b (fp32) ; h2 = bf16(relu(h1@W0+b)) (fp32 math)
    k_sgemm<BATCH, HID, DIN, 64, 64, 8, 4, 4, false, false><<<dim3(1, BATCH / 64), 256>>>(x,  W_emb, b_emb, h1);
    k_sgemm<BATCH, HID, HID, 64, 64, 8, 4, 4, true,  true ><<<dim3(1, BATCH / 64), 256>>>(h1, W0,    b0,    h2bf);

    // h3 = relu(h2 @ W1 + b1)           (HMMA bf16, K=64)
    k_hmma<HID, 2><<<dim3(CDIM / 128, BATCH / 128), 256>>>(
        h2bf, w1T, b1, nullptr, nullptr, nullptr, h3bf, CDIM);

    // mu = h3 @ W_mu + b_mu (+ musq)    (HMMA bf16, K=256)
    k_hmma<CDIM, 1><<<dim3(CDIM / 128, BATCH / 128), 256>>>(
        h3bf, wmuT, b_mu, nullptr, musq, nullptr, mubf, CDIM);

    // neg_d = 2*mu@protos^T - musq - psq  (HMMA bf16, K=256)
    k_hmma<CDIM, 0><<<dim3(KPROT / 128, BATCH / 128), 256>>>(
        mubf, protosbf, psq, musq, nullptr, negd, nullptr, KPROT);

    // per-row lse / argmax(neg_d+gumbel) / gather quantized rows
    k_rowfin<<<BATCH / 8, 256>>>(gumbel, protos, out);

    // per-proto column sums for prior / mean logprobs
    k_colsum<<<BATCH / 16, 256>>>();

    // scalar loss at the tail of the output buffer
    k_loss<<<1, 256>>>(out, out_size - 1);
}

// round 7
// speedup vs baseline: 4.3134x; 1.3132x over previous
#include <cuda_runtime.h>
#include <cuda_bf16.h>
#include <cuda_fp16.h>
#include <math.h>
#include <stdint.h>

#define BATCH 16384
#define DIN   512
#define HID   64
#define CDIM  256
#define KPROT 2048

// ---------------- scratch (no allocations allowed) ----------------
static __device__ __nv_bfloat16 g_xbf[BATCH * DIN];
static __device__ __nv_bfloat16 g_h1bf[BATCH * HID];
static __device__ __nv_bfloat16 g_h2bf[BATCH * HID];
static __device__ __nv_bfloat16 g_h3bf[BATCH * CDIM];
static __device__ __nv_bfloat16 g_mubf[BATCH * CDIM];
static __device__ __nv_bfloat16 g_protosbf[KPROT * CDIM];
static __device__ __nv_bfloat16 g_WembT[HID * DIN];
static __device__ __nv_bfloat16 g_W0T[HID * HID];
static __device__ __nv_bfloat16 g_W1T[CDIM * HID];
static __device__ __nv_bfloat16 g_WmuT[CDIM * CDIM];
static __device__ __half g_ndh[(size_t)BATCH * KPROT];   // 64 MB
static __device__ float g_psq[KPROT];
static __device__ float g_lse[BATCH];
static __device__ float g_cs_exp[KPROT];
static __device__ float g_mubar[CDIM];
static __device__ float g_colmn[KPROT];
static __device__ float g_sum_lse_d;

// ---------------- helpers ----------------
__device__ __forceinline__ uint32_t smem_to_u32(const void* p) {
    uint32_t a;
    asm("{ .reg .u64 t; cvta.to.shared.u64 t, %1; cvt.u32.u64 %0, t; }" : "=r"(a) : "l"(p));
    return a;
}
#define LDMATRIX_X4(R, addr) \
    asm volatile("ldmatrix.sync.aligned.m8n8.x4.shared.b16 {%0,%1,%2,%3}, [%4];" \
        : "=r"((R)[0]), "=r"((R)[1]), "=r"((R)[2]), "=r"((R)[3]) : "r"(addr))
#define MMA_BF16(D, A, B0, B1) \
    asm volatile("mma.sync.aligned.m16n8k16.row.col.f32.bf16.bf16.f32 " \
        "{%0,%1,%2,%3}, {%4,%5,%6,%7}, {%8,%9}, {%0,%1,%2,%3};" \
        : "+f"((D)[0]), "+f"((D)[1]), "+f"((D)[2]), "+f"((D)[3]) \
        : "r"((A)[0]), "r"((A)[1]), "r"((A)[2]), "r"((A)[3]), "r"(B0), "r"(B1))

// ---------------- init / conversions ----------------
__global__ void k_zero() {
    int t = blockIdx.x * 256 + threadIdx.x;
    if (t < KPROT) g_cs_exp[t] = 0.f;
    if (t < CDIM)  g_mubar[t] = 0.f;
    if (t == 0)    g_sum_lse_d = 0.f;
}
__global__ void k_cvt_x(const float* __restrict__ x) {
    int i = blockIdx.x * 256 + threadIdx.x;                // float4 index
    float4 v = ((const float4*)x)[i];
    __nv_bfloat162* o = (__nv_bfloat162*)g_xbf;
    o[2 * i]     = __floats2bfloat162_rn(v.x, v.y);
    o[2 * i + 1] = __floats2bfloat162_rn(v.z, v.w);
}
__global__ void k_cvt_protos(const float* __restrict__ p) {
    int i = blockIdx.x * 256 + threadIdx.x;
    g_protosbf[i] = __float2bfloat16(p[i]);
}
template<int R, int C>
__global__ void k_cvtT(const float* __restrict__ W, __nv_bfloat16* __restrict__ o) {
    int n = blockIdx.x, k = threadIdx.x;                   // o[C][R] = W[R][C]^T
    o[n * R + k] = __float2bfloat16(W[(size_t)k * C + n]);
}

// ---------------- bf16 HMMA GEMM (mma.sync m16n8k16), D = A @ B^T ----------
// A [*, KDIM] row-major bf16, B [*, KDIM] row-major bf16.
// Tile 128 x BN, BK=32, 8 warps (4 along M x 2 along N).
// EPI: 0 = NEGD  (half out: 2*acc - colterm[c])
//      1 = LIN   (bf16 out: acc + colterm[c])
//      2 = RELU  (bf16 out: max(acc + colterm[c], 0))
template<int KDIM, int BN, int EPI>
__global__ void __launch_bounds__(256, 2)
k_hmma(const __nv_bfloat16* __restrict__ A, const __nv_bfloat16* __restrict__ B,
       const float* __restrict__ colterm, void* __restrict__ outp, int ldOut)
{
    constexpr int NITER = KDIM / 32;
    constexpr int WN = BN / 2;       // cols per warp
    constexpr int NJ = BN / 16;      // n8 tiles per warp
    constexpr int NP = WN / 16;      // ldmatrix B panels per warp
    __shared__ __align__(16) uint8_t As[128 * 80];
    __shared__ __align__(16) uint8_t Bs[BN * 80];

    const int tid  = threadIdx.x;
    const int lane = tid & 31;
    const int wid  = tid >> 5;
    const int wm   = wid & 3;
    const int wn   = wid >> 2;
    const int m0   = blockIdx.y * 128;
    const int n0   = blockIdx.x * BN;
    const uint32_t asb = smem_to_u32(As);
    const uint32_t bsb = smem_to_u32(Bs);

    const int lrow = tid >> 2;
    const int lch  = tid & 3;
    const uint4* pa0 = (const uint4*)(A + (size_t)(m0 + lrow)      * KDIM);
    const uint4* pa1 = (const uint4*)(A + (size_t)(m0 + lrow + 64) * KDIM);
    const uint4* pb0 = (const uint4*)(B + (size_t)(n0 + lrow)      * KDIM);
    const uint4* pb1 = (BN == 128) ? (const uint4*)(B + (size_t)(n0 + lrow + 64) * KDIM) : pb0;
    uint4* sa0 = (uint4*)(As + lrow * 80 + lch * 16);
    uint4* sa1 = (uint4*)(As + (lrow + 64) * 80 + lch * 16);
    uint4* sb0 = (uint4*)(Bs + lrow * 80 + lch * 16);
    uint4* sb1 = (BN == 128) ? (uint4*)(Bs + (lrow + 64) * 80 + lch * 16) : sb0;

    *sa0 = pa0[lch]; *sa1 = pa1[lch];
    *sb0 = pb0[lch];
    if (BN == 128) *sb1 = pb1[lch];
    __syncthreads();

    float acc[2][NJ][4];
#pragma unroll
    for (int i = 0; i < 2; i++)
#pragma unroll
        for (int j = 0; j < NJ; j++)
#pragma unroll
            for (int q = 0; q < 4; q++) acc[i][j][q] = 0.f;

    const uint32_t aoff = (uint32_t)((wm * 32 + (lane & 15)) * 80 + (lane >> 4) * 16);
    const uint32_t boff = (uint32_t)((wn * WN + ((lane >> 4) & 1) * 8 + (lane & 7)) * 80
                                     + ((lane >> 3) & 1) * 16);

    for (int it = 0; it < NITER; it++) {
        uint4 fa0, fa1, fb0, fb1;
        if (it + 1 < NITER) {
            int ku = (it + 1) * 4 + lch;
            fa0 = pa0[ku]; fa1 = pa1[ku];
            fb0 = pb0[ku];
            if (BN == 128) fb1 = pb1[ku];
        }
#pragma unroll
        for (int ks = 0; ks < 2; ks++) {
            uint32_t af[2][4], bfr[NP][4];
            LDMATRIX_X4(af[0], asb + aoff + ks * 32);
            LDMATRIX_X4(af[1], asb + aoff + 16 * 80 + ks * 32);
#pragma unroll
            for (int p = 0; p < NP; p++)
                LDMATRIX_X4(bfr[p], bsb + boff + p * (16 * 80) + ks * 32);
#pragma unroll
            for (int im = 0; im < 2; im++)
#pragma unroll
                for (int jn = 0; jn < NJ; jn++)
                    MMA_BF16(acc[im][jn], af[im],
                             bfr[jn >> 1][(jn & 1) * 2], bfr[jn >> 1][(jn & 1) * 2 + 1]);
        }
        __syncthreads();
        if (it + 1 < NITER) {
            *sa0 = fa0; *sa1 = fa1; *sb0 = fb0;
            if (BN == 128) *sb1 = fb1;
            __syncthreads();
        }
    }

    // ---- epilogue ----
    const int r_base = m0 + wm * 32 + (lane >> 2);
    const int c_base = n0 + wn * WN + (lane & 3) * 2;
#pragma unroll
    for (int im = 0; im < 2; im++) {
        const int r0 = r_base + im * 16;
        const int r1 = r0 + 8;
#pragma unroll
        for (int jn = 0; jn < NJ; jn++) {
            const int c = c_base + jn * 8;
            const float ct0 = colterm[c], ct1 = colterm[c + 1];
            if (EPI == 0) {
                __half* oh = (__half*)outp;
                *(__half2*)(oh + (size_t)r0 * ldOut + c) =
                    __floats2half2_rn(2.f * acc[im][jn][0] - ct0, 2.f * acc[im][jn][1] - ct1);
                *(__half2*)(oh + (size_t)r1 * ldOut + c) =
                    __floats2half2_rn(2.f * acc[im][jn][2] - ct0, 2.f * acc[im][jn][3] - ct1);
            } else {
                float v00 = acc[im][jn][0] + ct0;
                float v01 = acc[im][jn][1] + ct1;
                float v10 = acc[im][jn][2] + ct0;
                float v11 = acc[im][jn][3] + ct1;
                if (EPI == 2) {
                    v00 = fmaxf(v00, 0.f); v01 = fmaxf(v01, 0.f);
                    v10 = fmaxf(v10, 0.f); v11 = fmaxf(v11, 0.f);
                }
                __nv_bfloat16* ob = (__nv_bfloat16*)outp;
                *(__nv_bfloat162*)(ob + (size_t)r0 * ldOut + c) = __floats2bfloat162_rn(v00, v01);
                *(__nv_bfloat162*)(ob + (size_t)r1 * ldOut + c) = __floats2bfloat162_rn(v10, v11);
            }
        }
    }
}

// ---------------- per-row sum of squares for protos ----------------
__global__ void k_rowsq(const float* __restrict__ X, float* __restrict__ out, int ncols)
{
    int row  = blockIdx.x * 8 + (threadIdx.x >> 5);
    int lane = threadIdx.x & 31;
    const float* p = X + (size_t)row * ncols;
    float s = 0.f;
    for (int c = lane; c < ncols; c += 32) { float v = p[c]; s = fmaf(v, v, s); }
#pragma unroll
    for (int o = 16; o > 0; o >>= 1) s += __shfl_xor_sync(0xffffffffu, s, o);
    if (lane == 0) out[row] = s;
}

// ---------------- mubar = sum_b mu[b,:] (scaled later) ----------------
__global__ void k_mubar() {
    int c = threadIdx.x;
    int r0 = blockIdx.x * 128;
    float s = 0.f;
    for (int r = 0; r < 128; r++)
        s += __bfloat162float(g_mubf[(size_t)(r0 + r) * CDIM + c]);
    atomicAdd(&g_mubar[c], s);
}

// ---------------- colmean_k(nd) = 2*mean(mu).p_k - psq_k ----------------
__global__ void k_colmean(const float* __restrict__ psq) {
    __shared__ float mb[CDIM];
    if (threadIdx.x < CDIM) mb[threadIdx.x] = g_mubar[threadIdx.x] * (1.f / BATCH);
    __syncthreads();
    int warp = threadIdx.x >> 5, lane = threadIdx.x & 31;
    int k = blockIdx.x * 8 + warp;
    uint4 pv = ((const uint4*)(g_protosbf + (size_t)k * CDIM))[lane];
    const __nv_bfloat16* pb = (const __nv_bfloat16*)&pv;
    float s = 0.f;
#pragma unroll
    for (int j = 0; j < 8; j++)
        s = fmaf(__bfloat162float(pb[j]), mb[lane * 8 + j], s);
#pragma unroll
    for (int o = 16; o > 0; o >>= 1) s += __shfl_xor_sync(0xffffffffu, s, o);
    if (lane == 0) g_colmn[k] = 2.f * s - psq[k];
}

// ---------------- per-row: lse, argmax(nd+gumbel), quantized gather --------
__global__ void __launch_bounds__(256) k_rowfin(const float* __restrict__ gumbel,
                                               const float* __restrict__ protos,
                                               float* __restrict__ outq)
{
    __shared__ float sL[8];
    int warp = threadIdx.x >> 5, lane = threadIdx.x & 31;
    int row  = blockIdx.x * 8 + warp;
    const __half2* nd = (const __half2*)(g_ndh + (size_t)row * KPROT);
    const float2*  gb = (const float2*)(gumbel + (size_t)row * KPROT);

    float2 vv[32];
    float m1 = -3.402823466e38f, m2 = -3.402823466e38f;
    int arg = 0;
#pragma unroll
    for (int i = 0; i < 32; i++) {
        int idx = lane + i * 32;
        float2 v = __half22float2(nd[idx]);
        vv[i] = v;
        m1 = fmaxf(m1, fmaxf(v.x, v.y));
        float2 g = gb[idx];
        float tx = v.x + g.x, ty = v.y + g.y;
        int cx = 2 * idx;
        if (tx > m2) { m2 = tx; arg = cx; }
        if (ty > m2) { m2 = ty; arg = cx + 1; }
    }
#pragma unroll
    for (int o = 16; o > 0; o >>= 1) {
        float om = __shfl_xor_sync(0xffffffffu, m2, o);
        int   oa = __shfl_xor_sync(0xffffffffu, arg, o);
        if (om > m2 || (om == m2 && oa < arg)) { m2 = om; arg = oa; }
    }
#pragma unroll
    for (int o = 16; o > 0; o >>= 1) m1 = fmaxf(m1, __shfl_xor_sync(0xffffffffu, m1, o));
    float s = 0.f;
#pragma unroll
    for (int i = 0; i < 32; i++)
        s += __expf(vv[i].x - m1) + __expf(vv[i].y - m1);
#pragma unroll
    for (int o = 16; o > 0; o >>= 1) s += __shfl_xor_sync(0xffffffffu, s, o);
    float lse = m1 + logf(s);
    if (lane == 0) { g_lse[row] = lse; sL[warp] = lse; }

    // quantized row = protos[arg] (hard + soft - stop_grad(soft) == hard, exactly)
    const float* pr = protos + (size_t)arg * CDIM;
    float* o = outq + (size_t)row * CDIM;
#pragma unroll
    for (int i = 0; i < CDIM / 32; i++) o[lane + i * 32] = pr[lane + i * 32];

    __syncthreads();
    if (threadIdx.x == 0) {
        float t = 0.f;
#pragma unroll
        for (int r = 0; r < 8; r++) t += sL[r];
        atomicAdd(&g_sum_lse_d, t);
    }
}

// ---------------- column sums of exp(nd - lse) ----------------
__global__ void __launch_bounds__(256) k_colsum()
{
    __shared__ float sL[64];
    int tid = threadIdx.x;
    int row0 = blockIdx.x * 64;
    if (tid < 64) sL[tid] = g_lse[row0 + tid];
    __syncthreads();
    float se[8];
#pragma unroll
    for (int j = 0; j < 8; j++) se[j] = 0.f;
    for (int r = 0; r < 64; r++) {
        const __half2* ndr = (const __half2*)(g_ndh + (size_t)(row0 + r) * KPROT);
        float l = sL[r];
#pragma unroll
        for (int j = 0; j < 4; j++) {
            float2 v = __half22float2(ndr[tid + j * 256]);
            se[2 * j]     += __expf(v.x - l);
            se[2 * j + 1] += __expf(v.y - l);
        }
    }
#pragma unroll
    for (int j = 0; j < 4; j++) {
        int c = 2 * (tid + j * 256);
        atomicAdd(&g_cs_exp[c],     se[2 * j]);
        atomicAdd(&g_cs_exp[c + 1], se[2 * j + 1]);
    }
}

// ---------------- final loss scalar ----------------
__global__ void k_loss(float* __restrict__ out, int loss_idx)
{
    __shared__ float r1[256], r2[256];
    int tid = threadIdx.x;
    const float inv = 1.f / (float)BATCH;
    float mean_lse = g_sum_lse_d * inv;
    float c1 = 0.f, c2 = 0.f;
    for (int k = tid; k < KPROT; k += 256) {
        float prior = g_cs_exp[k] * inv + 1e-6f;
        float Mk    = g_colmn[k] - mean_lse;     // mean_b logprobs[:,k]
        float lp    = logf(prior);
        c1 += prior * lp;
        c2 += prior * Mk;
    }
    r1[tid] = c1; r2[tid] = c2;
    __syncthreads();
    for (int o = 128; o > 0; o >>= 1) {
        if (tid < o) { r1[tid] += r1[tid + o]; r2[tid] += r2[tid + o]; }
        __syncthreads();
    }
    if (tid == 0) {
        float capacity = r1[0] - r2[0];
        float ent      = -r1[0];
        out[loss_idx]  = 0.01f * capacity + (-0.001f) * ent;
    }
}

// ---------------- launch ----------------
extern "C" void kernel_launch(void* const* d_in, const int* in_sizes, int n_in,
                              void* d_out, int out_size)
{
    (void)in_sizes; (void)n_in;
    const float* x      = (const float*)d_in[0];
    const float* gumbel = (const float*)d_in[1];
    const float* W_emb  = (const float*)d_in[2];
    const float* b_emb  = (const float*)d_in[3];
    const float* W0     = (const float*)d_in[4];
    const float* b0     = (const float*)d_in[5];
    const float* W1     = (const float*)d_in[6];
    const float* b1     = (const float*)d_in[7];
    const float* W_mu   = (const float*)d_in[8];
    const float* b_mu   = (const float*)d_in[9];
    // d_in[10], d_in[11] = W_var, b_var: dead code in the reference
    const float* protos = (const float*)d_in[12];
    float* out = (float*)d_out;

    float *psq;
    __nv_bfloat16 *xbf, *h1bf, *h2bf, *h3bf, *mubf, *protosbf, *wembT, *w0T, *w1T, *wmuT;
    __half* ndh;
    cudaGetSymbolAddress((void**)&xbf,      g_xbf);
    cudaGetSymbolAddress((void**)&h1bf,     g_h1bf);
    cudaGetSymbolAddress((void**)&h2bf,     g_h2bf);
    cudaGetSymbolAddress((void**)&h3bf,     g_h3bf);
    cudaGetSymbolAddress((void**)&mubf,     g_mubf);
    cudaGetSymbolAddress((void**)&protosbf, g_protosbf);
    cudaGetSymbolAddress((void**)&wembT,    g_WembT);
    cudaGetSymbolAddress((void**)&w0T,      g_W0T);
    cudaGetSymbolAddress((void**)&w1T,      g_W1T);
    cudaGetSymbolAddress((void**)&wmuT,     g_WmuT);
    cudaGetSymbolAddress((void**)&psq,      g_psq);
    cudaGetSymbolAddress((void**)&ndh,      g_ndh);

    k_zero<<<8, 256>>>();
    k_cvt_x<<<(BATCH * DIN / 4) / 256, 256>>>(x);
    k_cvt_protos<<<(KPROT * CDIM) / 256, 256>>>(protos);
    k_cvtT<DIN,  HID ><<<HID,  DIN >>>(W_emb, wembT);
    k_cvtT<HID,  HID ><<<HID,  HID >>>(W0,    w0T);
    k_cvtT<HID,  CDIM><<<CDIM, HID >>>(W1,    w1T);
    k_cvtT<CDIM, CDIM><<<CDIM, CDIM>>>(W_mu,  wmuT);
    k_rowsq<<<KPROT / 8, 256>>>(protos, psq, CDIM);

    // MLP, all HMMA bf16 (fp32 accumulate):
    // h1 = x@W_emb + b ; h2 = relu(h1@W0 + b) ; h3 = relu(h2@W1 + b) ; mu = h3@W_mu + b
    k_hmma<DIN,  64, 1><<<dim3(1, BATCH / 128), 256>>>(xbf,  wembT, b_emb, h1bf, HID);
    k_hmma<HID,  64, 2><<<dim3(1, BATCH / 128), 256>>>(h1bf, w0T,   b0,    h2bf, HID);
    k_hmma<HID, 128, 2><<<dim3(CDIM / 128, BATCH / 128), 256>>>(h2bf, w1T, b1,   h3bf, CDIM);
    k_hmma<CDIM,128, 1><<<dim3(CDIM / 128, BATCH / 128), 256>>>(h3bf, wmuT, b_mu, mubf, CDIM);

    // nd' = 2*mu@protos^T - psq  (row-constant musq dropped: softmax/argmax invariant)
    k_hmma<CDIM,128, 0><<<dim3(KPROT / 128, BATCH / 128), 256>>>(mubf, protosbf, psq, ndh, KPROT);

    // analytic colmean(nd') = 2*mean(mu).p_k - psq_k
    k_mubar<<<BATCH / 128, CDIM>>>();
    k_colmean<<<KPROT / 8, 256>>>(psq);

    // per-row lse / argmax(nd+gumbel) / gather quantized rows
    k_rowfin<<<BATCH / 8, 256>>>(gumbel, protos, out);

    // per-proto column sums of exp(nd - lse)
    k_colsum<<<BATCH / 64, 256>>>();

    // scalar loss at the tail of the output buffer
    k_loss<<<1, 256>>>(out, out_size - 1);
}